// round 3
// baseline (speedup 1.0000x reference)
#include <cuda_runtime.h>

// Temporal cosine regularizer, single fused kernel (R3: software-pipelined loads).
//   out = -0.02/(N-1) * sum_i <x_i,x_{i+1}> / (max(||x_i||,eps)*max(||x_{i+1}||,eps))
//
// HBM-bound, 512 MB read-once. R2 showed DRAM at 76.6% with regs=32: next-row
// loads were serialized behind the per-row shuffle-reduce chain. R3 explicitly
// prefetches row r+1 before reducing row r, with launch_bounds(256,4) to give
// ptxas the register budget (prev/cur/next = 24 floats) to keep 4+ LDG.128
// outstanding per warp.

#define COLS     2048
#define RPB      64
#define NTHREADS 256

__device__ float        g_partials[8192];
__device__ unsigned int g_count = 0;

__device__ __forceinline__ float warp_reduce_f(float v) {
#pragma unroll
    for (int o = 16; o > 0; o >>= 1) v += __shfl_xor_sync(0xffffffffu, v, o);
    return v;
}

__global__ void __launch_bounds__(NTHREADS, 4)
pair_dot_fused_kernel(const float* __restrict__ x, int N, float* __restrict__ out) {
    __shared__ float s_sq[RPB + 1][8];
    __shared__ float s_dp[RPB + 1][8];
    __shared__ bool  s_last;

    const int tid  = threadIdx.x;
    const int lane = tid & 31;
    const int warp = tid >> 5;
    const int r0   = blockIdx.x * RPB;

    // Per-thread column base (two float4 per row: tid and tid+256).
    const float4* base = reinterpret_cast<const float4*>(x) + tid;

    // Load row r0 -> prev, prefetch row r0+1 -> cur. (r0+1 always < N since
    // r0 <= N-RPB... guard via clamp for safety on the last block.)
    float prev[8], cur[8];
    {
        const float4* rp = base + (size_t)r0 * (COLS / 4);
        float4 a = __ldg(rp);
        float4 b = __ldg(rp + NTHREADS);
        long r1 = (r0 + 1 < N) ? r0 + 1 : N - 1;
        const float4* rn = base + (size_t)r1 * (COLS / 4);
        float4 c = __ldg(rn);
        float4 d = __ldg(rn + NTHREADS);
        prev[0]=a.x; prev[1]=a.y; prev[2]=a.z; prev[3]=a.w;
        prev[4]=b.x; prev[5]=b.y; prev[6]=b.z; prev[7]=b.w;
        cur[0]=c.x; cur[1]=c.y; cur[2]=c.z; cur[3]=c.w;
        cur[4]=d.x; cur[5]=d.y; cur[6]=d.z; cur[7]=d.w;
        float sq = 0.0f;
#pragma unroll
        for (int j = 0; j < 8; ++j) sq = fmaf(prev[j], prev[j], sq);
        sq = warp_reduce_f(sq);
        if (lane == 0) s_sq[0][warp] = sq;
    }

    // Pipelined mainloop: prefetch row r+1, compute row r, rotate.
#pragma unroll 2
    for (int rr = 1; rr <= RPB; ++rr) {
        const int r = r0 + rr;

        // Issue next row's loads FIRST (independent of everything below).
        long rnext = (r + 1 < N) ? r + 1 : N - 1;   // clamped; unused when OOB
        const float4* rn = base + (size_t)rnext * (COLS / 4);
        float4 c = __ldg(rn);
        float4 d = __ldg(rn + NTHREADS);

        // Compute with cur (row r) vs prev (row r-1).
        float sq = 0.0f, dp = 0.0f;
        if (r < N) {
#pragma unroll
            for (int j = 0; j < 8; ++j) {
                sq = fmaf(cur[j], cur[j], sq);
                dp = fmaf(cur[j], prev[j], dp);
            }
        }
        sq = warp_reduce_f(sq);
        dp = warp_reduce_f(dp);
        if (lane == 0) { s_sq[rr][warp] = sq; s_dp[rr][warp] = dp; }

        // Rotate buffers.
#pragma unroll
        for (int j = 0; j < 8; ++j) prev[j] = cur[j];
        cur[0]=c.x; cur[1]=c.y; cur[2]=c.z; cur[3]=c.w;
        cur[4]=d.x; cur[5]=d.y; cur[6]=d.z; cur[7]=d.w;
    }
    __syncthreads();

    // Warp 0: combine 8 warp-partials per row, cosine terms, fp64 accumulate.
    if (warp == 0) {
        double acc = 0.0;
        for (int rr = 1 + lane; rr <= RPB; rr += 32) {
            if (r0 + rr < N) {  // dot index r0+rr-1 must be <= N-2
                float n2a = 0.0f, n2b = 0.0f, d8 = 0.0f;
#pragma unroll
                for (int w = 0; w < 8; ++w) {
                    n2a += s_sq[rr - 1][w];
                    n2b += s_sq[rr][w];
                    d8  += s_dp[rr][w];
                }
                float na = fmaxf(sqrtf(n2a), 1e-12f);
                float nb = fmaxf(sqrtf(n2b), 1e-12f);
                acc += (double)(d8 / (na * nb));
            }
        }
#pragma unroll
        for (int o = 16; o > 0; o >>= 1)
            acc += __shfl_xor_sync(0xffffffffu, acc, o);
        if (lane == 0) g_partials[blockIdx.x] = (float)acc;
    }

    // ---- last-block-done: deterministic final reduction in this kernel ----
    __threadfence();
    if (tid == 0) {
        unsigned int prev_cnt = atomicAdd(&g_count, 1u);
        s_last = (prev_cnt == gridDim.x - 1);
    }
    __syncthreads();

    if (s_last) {
        __shared__ double s[NTHREADS];
        const int nb = gridDim.x;
        double a = 0.0;
        for (int i = tid; i < nb; i += NTHREADS)
            a += (double)__ldcg(&g_partials[i]);
        s[tid] = a;
        __syncthreads();
#pragma unroll
        for (int o = NTHREADS / 2; o > 0; o >>= 1) {
            if (tid < o) s[tid] += s[tid + o];
            __syncthreads();
        }
        if (tid == 0) {
            out[0] = (float)(-2.0 * 0.01 * s[0] / (double)(N - 1));
            g_count = 0;  // reset for next graph replay
        }
    }
}

extern "C" void kernel_launch(void* const* d_in, const int* in_sizes, int n_in,
                              void* d_out, int out_size) {
    const float* x = (const float*)d_in[0];
    const int N = in_sizes[0] / COLS;            // 65536
    const int nblocks = (N - 1 + RPB - 1) / RPB; // 1024
    pair_dot_fused_kernel<<<nblocks, NTHREADS>>>(x, N, (float*)d_out);
}

// round 4
// speedup vs baseline: 1.1314x; 1.1314x over previous
#include <cuda_runtime.h>

// Temporal cosine regularizer, single fused kernel (R4: cp.async smem ring).
//   out = -0.02/(N-1) * sum_i <x_i,x_{i+1}> / (max(||x_i||,eps)*max(||x_{i+1}||,eps))
//
// HBM-bound, 512 MB read-once. R2 (register pipeline, occ 83%) hit 76.6% DRAM:
// each warp only has loads outstanding during its load-wait phase; during the
// FMA+shuffle chain it contributes no MLP (duty ~0.75 == measured DRAM%).
// R3 (deeper register prefetch) halved occupancy and regressed.
// R4 moves in-flight data to SMEM via cp.async (LDGSTS): 3-stage ring,
// zero register cost for in-flight rows, no __syncthreads in the pipeline
// (threads read back only their own copied bytes; wait_group orders them).

#define COLS     2048
#define RPB      64
#define NTHREADS 256
#define STAGES   3

__device__ float        g_partials[8192];
__device__ unsigned int g_count = 0;

__device__ __forceinline__ void cp_async16(void* smem_dst, const void* gmem_src) {
    unsigned int s = (unsigned int)__cvta_generic_to_shared(smem_dst);
    asm volatile("cp.async.cg.shared.global [%0], [%1], 16;" :: "r"(s), "l"(gmem_src));
}

__device__ __forceinline__ float warp_reduce_f(float v) {
#pragma unroll
    for (int o = 16; o > 0; o >>= 1) v += __shfl_xor_sync(0xffffffffu, v, o);
    return v;
}

__global__ void __launch_bounds__(NTHREADS, 8)
pair_dot_fused_kernel(const float* __restrict__ x, int N, float* __restrict__ out) {
    __shared__ __align__(16) float buf[STAGES][COLS];   // 24 KB ring
    __shared__ __align__(16) float s_sq[RPB + 1][8];    // aliased by finalize
    __shared__ __align__(16) float s_dp[RPB + 1][8];
    __shared__ bool s_last;

    const int tid  = threadIdx.x;
    const int lane = tid & 31;
    const int warp = tid >> 5;
    const int r0   = blockIdx.x * RPB;

    const int c0 = tid * 4;               // float index of this thread's 1st float4
    const int c1 = (tid + NTHREADS) * 4;  // 2nd float4

    // ---- prologue: issue rows r0 .. r0+STAGES-2 into stages 0..STAGES-2 ----
#pragma unroll
    for (int p = 0; p < STAGES - 1; ++p) {
        int r = r0 + p; if (r > N - 1) r = N - 1;       // clamp (dup row, discarded)
        const float* src = x + (size_t)r * COLS;
        cp_async16(&buf[p][c0], src + c0);
        cp_async16(&buf[p][c1], src + c1);
        asm volatile("cp.async.commit_group;");
    }

    float prev[8] = {0,0,0,0,0,0,0,0};

    // ---- pipelined mainloop over rows r0+k, k = 0..RPB ----
#pragma unroll 3
    for (int k = 0; k <= RPB; ++k) {
        // Always issue+commit (clamped row) so group counting stays uniform
        // and wait_group<STAGES-2> always implies row k's group is complete.
        {
            int r = r0 + k + STAGES - 1; if (r > N - 1) r = N - 1;
            const float* src = x + (size_t)r * COLS;
            const int sw = (k + STAGES - 1) % STAGES;   // overwrites consumed row k-1
            cp_async16(&buf[sw][c0], src + c0);
            cp_async16(&buf[sw][c1], src + c1);
            asm volatile("cp.async.commit_group;");
        }
        asm volatile("cp.async.wait_group %0;" :: "n"(STAGES - 2));

        // Each thread reads only the bytes it copied: no __syncthreads needed.
        const int s = k % STAGES;
        float4 a = *reinterpret_cast<const float4*>(&buf[s][c0]);
        float4 b = *reinterpret_cast<const float4*>(&buf[s][c1]);
        float cur[8] = {a.x, a.y, a.z, a.w, b.x, b.y, b.z, b.w};

        float sq = 0.0f, dp = 0.0f;
        if (r0 + k < N) {
#pragma unroll
            for (int j = 0; j < 8; ++j) {
                sq = fmaf(cur[j], cur[j], sq);
                dp = fmaf(cur[j], prev[j], dp);
            }
        }
        sq = warp_reduce_f(sq);
        dp = warp_reduce_f(dp);
        if (lane == 0) { s_sq[k][warp] = sq; s_dp[k][warp] = dp; }

#pragma unroll
        for (int j = 0; j < 8; ++j) prev[j] = cur[j];
    }
    __syncthreads();

    // ---- warp 0: per-row cosine terms, fp64 accumulate ----
    if (warp == 0) {
        double acc = 0.0;
        for (int rr = 1 + lane; rr <= RPB; rr += 32) {
            if (r0 + rr < N) {                 // dot index r0+rr-1 <= N-2
                float n2a = 0.0f, n2b = 0.0f, d8 = 0.0f;
#pragma unroll
                for (int w = 0; w < 8; ++w) {
                    n2a += s_sq[rr - 1][w];
                    n2b += s_sq[rr][w];
                    d8  += s_dp[rr][w];
                }
                float na = fmaxf(sqrtf(n2a), 1e-12f);
                float nb = fmaxf(sqrtf(n2b), 1e-12f);
                acc += (double)(d8 / (na * nb));
            }
        }
#pragma unroll
        for (int o = 16; o > 0; o >>= 1)
            acc += __shfl_xor_sync(0xffffffffu, acc, o);
        if (lane == 0) g_partials[blockIdx.x] = (float)acc;
    }

    // ---- last-block-done: deterministic final reduction ----
    __threadfence();
    if (tid == 0) {
        unsigned int prev_cnt = atomicAdd(&g_count, 1u);
        s_last = (prev_cnt == gridDim.x - 1);
    }
    __syncthreads();

    if (s_last) {
        // Reuse s_sq/s_dp storage (dead here) as 256 doubles (2 KB of 4.2 KB).
        double* sd = reinterpret_cast<double*>(&s_sq[0][0]);
        const int nb = gridDim.x;
        double a = 0.0;
        for (int i = tid; i < nb; i += NTHREADS)
            a += (double)__ldcg(&g_partials[i]);
        sd[tid] = a;
        __syncthreads();
#pragma unroll
        for (int o = NTHREADS / 2; o > 0; o >>= 1) {
            if (tid < o) sd[tid] += sd[tid + o];
            __syncthreads();
        }
        if (tid == 0) {
            out[0] = (float)(-2.0 * 0.01 * sd[0] / (double)(N - 1));
            g_count = 0;  // reset for next graph replay
        }
    }
}

extern "C" void kernel_launch(void* const* d_in, const int* in_sizes, int n_in,
                              void* d_out, int out_size) {
    const float* x = (const float*)d_in[0];
    const int N = in_sizes[0] / COLS;            // 65536
    const int nblocks = (N - 1 + RPB - 1) / RPB; // 1024
    pair_dot_fused_kernel<<<nblocks, NTHREADS>>>(x, N, (float*)d_out);
}